// round 4
// baseline (speedup 1.0000x reference)
#include <cuda_runtime.h>
#include <cuda_fp16.h>

// RoIAlign via NHWC fp16 relayout + branch-free gather.
// feat: (B=2, C=256, H=200, W=336) fp32 NCHW
// rois: (N=1000, 5) [bidx, x1, y1, x2, y2] fp32
// out:  (N, 256, 7, 7) fp32

#define B_    2
#define C_    256
#define H_    200
#define W_    336
#define OUTH  7
#define OUTW  7
#define NBIN  49
#define HWC   (H_ * W_ * C_)
#define CHALF 128

// NHWC fp16 scratch: [B][H][W][C]
__device__ __half g_feat16[(size_t)B_ * HWC];

// ---------------------------------------------------------------------------
// Kernel 1: NCHW fp32 -> NHWC fp16. Block: 64 channels x 32 x-positions.
// ---------------------------------------------------------------------------
__global__ __launch_bounds__(256) void transpose_kernel(const float* __restrict__ feat)
{
    __shared__ float tile[64][33];   // [c][x]

    int xt = blockIdx.x * 32;
    int by = blockIdx.y;             // b*H + y
    int b  = by / H_;
    int y  = by % H_;
    int c0 = blockIdx.z * 64;
    int tx = threadIdx.x;
    int ty = threadIdx.y;

    const float* src = feat + ((size_t)(b * C_ + c0) * H_ + y) * W_;
    int  xg  = xt + tx;
    bool xin = xg < W_;

    #pragma unroll
    for (int k = 0; k < 8; k++) {
        int c = ty + k * 8;
        tile[c][tx] = xin ? __ldg(src + (size_t)c * (H_ * W_) + xg) : 0.0f;
    }
    __syncthreads();

    __half* dst = g_feat16 + ((size_t)(b * H_ + y) * W_) * C_ + c0;
    #pragma unroll
    for (int k = 0; k < 4; k++) {
        int xl = ty + k * 8;
        int x  = xt + xl;
        if (x < W_) {
            __half2 v = __floats2half2_rn(tile[2 * tx][xl], tile[2 * tx + 1][xl]);
            *(__half2*)(dst + (size_t)x * C_ + 2 * tx) = v;
        }
    }
}

// ---------------------------------------------------------------------------
// Kernel 2: gather. grid (N, 2): roi x channel-half. 256 threads = 8 warps.
// Each warp serves 2 bins per pass: lanes 0-15 -> bin A, lanes 16-31 -> bin B.
// Lane covers 8 channels (uint4 = 16B of fp16). Branch-free coords in smem.
// ---------------------------------------------------------------------------
__global__ __launch_bounds__(256, 6) void roi_gather_kernel(
    const float* __restrict__ rois,
    float* __restrict__ out)
{
    __shared__ float sout[CHALF * NBIN + 16];  // bank-skewed: idx = c*49 + c/8 + bin
    __shared__ int   s_ylo[14], s_yhi[14], s_xlo[14], s_xhi[14];
    __shared__ float s_wy0[14], s_wy1[14], s_wx0[14], s_wx1[14];

    int n    = blockIdx.x;
    int half = blockIdx.y;
    int tid  = threadIdx.x;
    int warp = tid >> 5;
    int lane = tid & 31;

    const float* r = rois + n * 5;
    int   b  = (int)__ldg(r + 0);
    float sx = __ldg(r + 1) * 0.25f - 0.5f;
    float sy = __ldg(r + 2) * 0.25f - 0.5f;
    float ex = __ldg(r + 3) * 0.25f - 0.5f;
    float ey = __ldg(r + 4) * 0.25f - 0.5f;
    float bw = (ex - sx) / (float)OUTW;
    float bh = (ey - sy) / (float)OUTH;

    if (tid < 14) {
        int s  = tid;
        int ph = s >> 1, iy = s & 1;
        float y = sy + ((float)ph + (0.25f + 0.5f * iy)) * bh;
        bool valid = (y > -1.0f) && (y < (float)H_);
        float y0 = fmaxf(y, 0.0f);
        int ylo = (int)floorf(y0);
        int yhi; float ly;
        if (ylo >= H_ - 1) { ylo = H_ - 1; yhi = H_ - 1; ly = 0.0f; }
        else               { yhi = ylo + 1; ly = y0 - (float)ylo; }
        s_ylo[s] = ylo * (W_ * C_);
        s_yhi[s] = yhi * (W_ * C_);
        s_wy0[s] = valid ? (1.0f - ly) * 0.25f : 0.0f;
        s_wy1[s] = valid ? ly * 0.25f : 0.0f;
    } else if (tid >= 64 && tid < 78) {
        int s  = tid - 64;
        int pw = s >> 1, ix = s & 1;
        float x = sx + ((float)pw + (0.25f + 0.5f * ix)) * bw;
        bool valid = (x > -1.0f) && (x < (float)W_);
        float x0 = fmaxf(x, 0.0f);
        int xlo = (int)floorf(x0);
        int xhi; float lx;
        if (xlo >= W_ - 1) { xlo = W_ - 1; xhi = W_ - 1; lx = 0.0f; }
        else               { xhi = xlo + 1; lx = x0 - (float)xlo; }
        s_xlo[s] = xlo * C_;
        s_xhi[s] = xhi * C_;
        s_wx0[s] = valid ? (1.0f - lx) : 0.0f;
        s_wx1[s] = valid ? lx : 0.0f;
    }
    __syncthreads();

    // lane -> 8 channels within this half; lanes 16-31 handle the odd bin.
    int clane = (lane & 15) * 8;
    const __half* fbase = g_feat16 + (size_t)b * HWC + half * CHALF + clane;

    #pragma unroll
    for (int pass = 0; pass < 4; pass++) {
        int bin = pass * 16 + warp * 2 + (lane >> 4);
        bool active = bin < NBIN;
        int binc = active ? bin : 0;          // clamp for safe smem coord reads
        int ph = binc / OUTW;
        int pw = binc - ph * OUTW;

        float a0 = 0.f, a1 = 0.f, a2 = 0.f, a3 = 0.f;
        float a4 = 0.f, a5 = 0.f, a6 = 0.f, a7 = 0.f;

        #pragma unroll
        for (int iy = 0; iy < 2; iy++) {
            int   syi = ph * 2 + iy;
            int   yo0 = s_ylo[syi], yo1 = s_yhi[syi];
            float wy0 = s_wy0[syi], wy1 = s_wy1[syi];

            #pragma unroll
            for (int ix = 0; ix < 2; ix++) {
                int   sxi = pw * 2 + ix;
                int   xo0 = s_xlo[sxi], xo1 = s_xhi[sxi];
                float wx0 = s_wx0[sxi], wx1 = s_wx1[sxi];

                uint4 u00 = *(const uint4*)(fbase + yo0 + xo0);
                uint4 u01 = *(const uint4*)(fbase + yo0 + xo1);
                uint4 u10 = *(const uint4*)(fbase + yo1 + xo0);
                uint4 u11 = *(const uint4*)(fbase + yo1 + xo1);

                float w00 = wy0 * wx0, w01 = wy0 * wx1;
                float w10 = wy1 * wx0, w11 = wy1 * wx1;

                float2 t;
                t = __half22float2(*reinterpret_cast<__half2*>(&u00.x)); a0 += w00 * t.x; a1 += w00 * t.y;
                t = __half22float2(*reinterpret_cast<__half2*>(&u00.y)); a2 += w00 * t.x; a3 += w00 * t.y;
                t = __half22float2(*reinterpret_cast<__half2*>(&u00.z)); a4 += w00 * t.x; a5 += w00 * t.y;
                t = __half22float2(*reinterpret_cast<__half2*>(&u00.w)); a6 += w00 * t.x; a7 += w00 * t.y;

                t = __half22float2(*reinterpret_cast<__half2*>(&u01.x)); a0 += w01 * t.x; a1 += w01 * t.y;
                t = __half22float2(*reinterpret_cast<__half2*>(&u01.y)); a2 += w01 * t.x; a3 += w01 * t.y;
                t = __half22float2(*reinterpret_cast<__half2*>(&u01.z)); a4 += w01 * t.x; a5 += w01 * t.y;
                t = __half22float2(*reinterpret_cast<__half2*>(&u01.w)); a6 += w01 * t.x; a7 += w01 * t.y;

                t = __half22float2(*reinterpret_cast<__half2*>(&u10.x)); a0 += w10 * t.x; a1 += w10 * t.y;
                t = __half22float2(*reinterpret_cast<__half2*>(&u10.y)); a2 += w10 * t.x; a3 += w10 * t.y;
                t = __half22float2(*reinterpret_cast<__half2*>(&u10.z)); a4 += w10 * t.x; a5 += w10 * t.y;
                t = __half22float2(*reinterpret_cast<__half2*>(&u10.w)); a6 += w10 * t.x; a7 += w10 * t.y;

                t = __half22float2(*reinterpret_cast<__half2*>(&u11.x)); a0 += w11 * t.x; a1 += w11 * t.y;
                t = __half22float2(*reinterpret_cast<__half2*>(&u11.y)); a2 += w11 * t.x; a3 += w11 * t.y;
                t = __half22float2(*reinterpret_cast<__half2*>(&u11.z)); a4 += w11 * t.x; a5 += w11 * t.y;
                t = __half22float2(*reinterpret_cast<__half2*>(&u11.w)); a6 += w11 * t.x; a7 += w11 * t.y;
            }
        }

        if (active) {
            // skew: idx(c,bin) = c*49 + c/8 + bin -> lane stride 393 words, conflict-free
            int base = clane * NBIN + (clane >> 3) + bin;
            sout[base]            = a0;
            sout[base + NBIN]     = a1;
            sout[base + 2 * NBIN] = a2;
            sout[base + 3 * NBIN] = a3;
            sout[base + 4 * NBIN] = a4;
            sout[base + 5 * NBIN] = a5;
            sout[base + 6 * NBIN] = a6;
            sout[base + 7 * NBIN] = a7;
        }
    }
    __syncthreads();

    // coalesced writeout: this block owns out[n, half*128 : half*128+128, :, :]
    float* o = out + (size_t)n * (C_ * NBIN) + (size_t)half * CHALF * NBIN;
    #pragma unroll 7
    for (int i = tid; i < CHALF * NBIN; i += 256) {
        int c = i / NBIN;
        o[i] = sout[i + (c >> 3)];
    }
}

extern "C" void kernel_launch(void* const* d_in, const int* in_sizes, int n_in,
                              void* d_out, int out_size)
{
    const float* feat = (const float*)d_in[0];
    const float* rois = (const float*)d_in[1];
    float* out = (float*)d_out;

    dim3 tgrid((W_ + 31) / 32, B_ * H_, C_ / 64);
    dim3 tblock(32, 8);
    transpose_kernel<<<tgrid, tblock>>>(feat);

    int n_rois = in_sizes[1] / 5;
    dim3 ggrid(n_rois, 2);
    roi_gather_kernel<<<ggrid, 256>>>(rois, out);
}

// round 5
// speedup vs baseline: 1.6307x; 1.6307x over previous
#include <cuda_runtime.h>
#include <cuda_fp16.h>

// RoIAlign via NHWC fp16 relayout + branch-free gather (round-2 structure).
// feat: (B=2, C=256, H=200, W=336) fp32 NCHW
// rois: (N=1000, 5) [bidx, x1, y1, x2, y2] fp32
// out:  (N, 256, 7, 7) fp32

#define B_    2
#define C_    256
#define H_    200
#define W_    336
#define OUTH  7
#define OUTW  7
#define NBIN  49
#define HWC   (H_ * W_ * C_)
#define CHALF 128

// NHWC fp16 scratch: [B][H][W][C]
__device__ __half g_feat16[(size_t)B_ * HWC];

// ---------------------------------------------------------------------------
// Kernel 1: NCHW fp32 -> NHWC fp16. Block: 64 channels x 32 x-positions.
// ---------------------------------------------------------------------------
__global__ __launch_bounds__(256) void transpose_kernel(const float* __restrict__ feat)
{
    __shared__ float tile[64][33];   // [c][x]

    int xt = blockIdx.x * 32;
    int by = blockIdx.y;             // b*H + y
    int b  = by / H_;
    int y  = by % H_;
    int c0 = blockIdx.z * 64;
    int tx = threadIdx.x;
    int ty = threadIdx.y;

    const float* src = feat + ((size_t)(b * C_ + c0) * H_ + y) * W_;
    int  xg  = xt + tx;
    bool xin = xg < W_;

    #pragma unroll
    for (int k = 0; k < 8; k++) {
        int c = ty + k * 8;
        tile[c][tx] = xin ? __ldg(src + (size_t)c * (H_ * W_) + xg) : 0.0f;
    }
    __syncthreads();

    __half* dst = g_feat16 + ((size_t)(b * H_ + y) * W_) * C_ + c0;
    #pragma unroll
    for (int k = 0; k < 4; k++) {
        int xl = ty + k * 8;
        int x  = xt + xl;
        if (x < W_) {
            __half2 v = __floats2half2_rn(tile[2 * tx][xl], tile[2 * tx + 1][xl]);
            *(__half2*)(dst + (size_t)x * C_ + 2 * tx) = v;
        }
    }
}

// ---------------------------------------------------------------------------
// Kernel 2: gather. grid (N, 2): roi x channel-half. 256 threads = 8 warps.
// One bin per warp per iteration (bins warp, warp+8, ...). Lane covers 4
// channels (uint2 = 8B fp16) -> each corner is one contiguous 256B warp
// request. Coordinates precomputed branch-free in smem; validity and the
// 1/4 averaging factor folded into the weights.
// ---------------------------------------------------------------------------
__global__ __launch_bounds__(256) void roi_gather_kernel(
    const float* __restrict__ rois,
    float* __restrict__ out)
{
    __shared__ float sout[CHALF * NBIN + 32];  // skewed: idx = c*49 + c/4 + bin
    __shared__ int   s_ylo[14], s_yhi[14], s_xlo[14], s_xhi[14];
    __shared__ float s_wy0[14], s_wy1[14], s_wx0[14], s_wx1[14];

    int n    = blockIdx.x;
    int half = blockIdx.y;
    int tid  = threadIdx.x;
    int warp = tid >> 5;
    int lane = tid & 31;

    const float* r = rois + n * 5;
    int   b  = (int)__ldg(r + 0);
    float sx = __ldg(r + 1) * 0.25f - 0.5f;
    float sy = __ldg(r + 2) * 0.25f - 0.5f;
    float ex = __ldg(r + 3) * 0.25f - 0.5f;
    float ey = __ldg(r + 4) * 0.25f - 0.5f;
    float bw = (ex - sx) / (float)OUTW;
    float bh = (ey - sy) / (float)OUTH;

    if (tid < 14) {
        int s  = tid;
        int ph = s >> 1, iy = s & 1;
        float y = sy + ((float)ph + (0.25f + 0.5f * iy)) * bh;
        bool valid = (y > -1.0f) && (y < (float)H_);
        float y0 = fmaxf(y, 0.0f);
        int ylo = (int)floorf(y0);
        int yhi; float ly;
        if (ylo >= H_ - 1) { ylo = H_ - 1; yhi = H_ - 1; ly = 0.0f; }
        else               { yhi = ylo + 1; ly = y0 - (float)ylo; }
        s_ylo[s] = ylo * (W_ * C_);
        s_yhi[s] = yhi * (W_ * C_);
        s_wy0[s] = valid ? (1.0f - ly) * 0.25f : 0.0f;
        s_wy1[s] = valid ? ly * 0.25f : 0.0f;
    } else if (tid >= 64 && tid < 78) {
        int s  = tid - 64;
        int pw = s >> 1, ix = s & 1;
        float x = sx + ((float)pw + (0.25f + 0.5f * ix)) * bw;
        bool valid = (x > -1.0f) && (x < (float)W_);
        float x0 = fmaxf(x, 0.0f);
        int xlo = (int)floorf(x0);
        int xhi; float lx;
        if (xlo >= W_ - 1) { xlo = W_ - 1; xhi = W_ - 1; lx = 0.0f; }
        else               { xhi = xlo + 1; lx = x0 - (float)xlo; }
        s_xlo[s] = xlo * C_;
        s_xhi[s] = xhi * C_;
        s_wx0[s] = valid ? (1.0f - lx) : 0.0f;
        s_wx1[s] = valid ? lx : 0.0f;
    }
    __syncthreads();

    // lane -> 4 channels within this half
    int clane = lane * 4;
    const __half* fbase = g_feat16 + (size_t)b * HWC + half * CHALF + clane;

    for (int bin = warp; bin < NBIN; bin += 8) {
        int ph = bin / OUTW;
        int pw = bin - ph * OUTW;

        int   yA = s_ylo[ph * 2],     yB = s_yhi[ph * 2];
        int   yC = s_ylo[ph * 2 + 1], yD = s_yhi[ph * 2 + 1];
        float wyA0 = s_wy0[ph * 2],     wyA1 = s_wy1[ph * 2];
        float wyB0 = s_wy0[ph * 2 + 1], wyB1 = s_wy1[ph * 2 + 1];

        int   xA = s_xlo[pw * 2],     xB = s_xhi[pw * 2];
        int   xC = s_xlo[pw * 2 + 1], xD = s_xhi[pw * 2 + 1];
        float wxA0 = s_wx0[pw * 2],     wxA1 = s_wx1[pw * 2];
        float wxB0 = s_wx0[pw * 2 + 1], wxB1 = s_wx1[pw * 2 + 1];

        // 16 independent 8B loads (4 per sample point), issued as one batch
        uint2 uA00 = *(const uint2*)(fbase + yA + xA);
        uint2 uA01 = *(const uint2*)(fbase + yA + xB);
        uint2 uA10 = *(const uint2*)(fbase + yB + xA);
        uint2 uA11 = *(const uint2*)(fbase + yB + xB);

        uint2 uB00 = *(const uint2*)(fbase + yA + xC);
        uint2 uB01 = *(const uint2*)(fbase + yA + xD);
        uint2 uB10 = *(const uint2*)(fbase + yB + xC);
        uint2 uB11 = *(const uint2*)(fbase + yB + xD);

        uint2 uC00 = *(const uint2*)(fbase + yC + xA);
        uint2 uC01 = *(const uint2*)(fbase + yC + xB);
        uint2 uC10 = *(const uint2*)(fbase + yD + xA);
        uint2 uC11 = *(const uint2*)(fbase + yD + xB);

        uint2 uD00 = *(const uint2*)(fbase + yC + xC);
        uint2 uD01 = *(const uint2*)(fbase + yC + xD);
        uint2 uD10 = *(const uint2*)(fbase + yD + xC);
        uint2 uD11 = *(const uint2*)(fbase + yD + xD);

        float a0 = 0.f, a1 = 0.f, a2 = 0.f, a3 = 0.f;
        float2 t;

        // sample A: (iy=0, ix=0)
        {
            float w00 = wyA0 * wxA0, w01 = wyA0 * wxA1;
            float w10 = wyA1 * wxA0, w11 = wyA1 * wxA1;
            t = __half22float2(*reinterpret_cast<__half2*>(&uA00.x)); a0 += w00 * t.x; a1 += w00 * t.y;
            t = __half22float2(*reinterpret_cast<__half2*>(&uA00.y)); a2 += w00 * t.x; a3 += w00 * t.y;
            t = __half22float2(*reinterpret_cast<__half2*>(&uA01.x)); a0 += w01 * t.x; a1 += w01 * t.y;
            t = __half22float2(*reinterpret_cast<__half2*>(&uA01.y)); a2 += w01 * t.x; a3 += w01 * t.y;
            t = __half22float2(*reinterpret_cast<__half2*>(&uA10.x)); a0 += w10 * t.x; a1 += w10 * t.y;
            t = __half22float2(*reinterpret_cast<__half2*>(&uA10.y)); a2 += w10 * t.x; a3 += w10 * t.y;
            t = __half22float2(*reinterpret_cast<__half2*>(&uA11.x)); a0 += w11 * t.x; a1 += w11 * t.y;
            t = __half22float2(*reinterpret_cast<__half2*>(&uA11.y)); a2 += w11 * t.x; a3 += w11 * t.y;
        }
        // sample B: (iy=0, ix=1)
        {
            float w00 = wyA0 * wxB0, w01 = wyA0 * wxB1;
            float w10 = wyA1 * wxB0, w11 = wyA1 * wxB1;
            t = __half22float2(*reinterpret_cast<__half2*>(&uB00.x)); a0 += w00 * t.x; a1 += w00 * t.y;
            t = __half22float2(*reinterpret_cast<__half2*>(&uB00.y)); a2 += w00 * t.x; a3 += w00 * t.y;
            t = __half22float2(*reinterpret_cast<__half2*>(&uB01.x)); a0 += w01 * t.x; a1 += w01 * t.y;
            t = __half22float2(*reinterpret_cast<__half2*>(&uB01.y)); a2 += w01 * t.x; a3 += w01 * t.y;
            t = __half22float2(*reinterpret_cast<__half2*>(&uB10.x)); a0 += w10 * t.x; a1 += w10 * t.y;
            t = __half22float2(*reinterpret_cast<__half2*>(&uB10.y)); a2 += w10 * t.x; a3 += w10 * t.y;
            t = __half22float2(*reinterpret_cast<__half2*>(&uB11.x)); a0 += w11 * t.x; a1 += w11 * t.y;
            t = __half22float2(*reinterpret_cast<__half2*>(&uB11.y)); a2 += w11 * t.x; a3 += w11 * t.y;
        }
        // sample C: (iy=1, ix=0)
        {
            float w00 = wyB0 * wxA0, w01 = wyB0 * wxA1;
            float w10 = wyB1 * wxA0, w11 = wyB1 * wxA1;
            t = __half22float2(*reinterpret_cast<__half2*>(&uC00.x)); a0 += w00 * t.x; a1 += w00 * t.y;
            t = __half22float2(*reinterpret_cast<__half2*>(&uC00.y)); a2 += w00 * t.x; a3 += w00 * t.y;
            t = __half22float2(*reinterpret_cast<__half2*>(&uC01.x)); a0 += w01 * t.x; a1 += w01 * t.y;
            t = __half22float2(*reinterpret_cast<__half2*>(&uC01.y)); a2 += w01 * t.x; a3 += w01 * t.y;
            t = __half22float2(*reinterpret_cast<__half2*>(&uC10.x)); a0 += w10 * t.x; a1 += w10 * t.y;
            t = __half22float2(*reinterpret_cast<__half2*>(&uC10.y)); a2 += w10 * t.x; a3 += w10 * t.y;
            t = __half22float2(*reinterpret_cast<__half2*>(&uC11.x)); a0 += w11 * t.x; a1 += w11 * t.y;
            t = __half22float2(*reinterpret_cast<__half2*>(&uC11.y)); a2 += w11 * t.x; a3 += w11 * t.y;
        }
        // sample D: (iy=1, ix=1)
        {
            float w00 = wyB0 * wxB0, w01 = wyB0 * wxB1;
            float w10 = wyB1 * wxB0, w11 = wyB1 * wxB1;
            t = __half22float2(*reinterpret_cast<__half2*>(&uD00.x)); a0 += w00 * t.x; a1 += w00 * t.y;
            t = __half22float2(*reinterpret_cast<__half2*>(&uD00.y)); a2 += w00 * t.x; a3 += w00 * t.y;
            t = __half22float2(*reinterpret_cast<__half2*>(&uD01.x)); a0 += w01 * t.x; a1 += w01 * t.y;
            t = __half22float2(*reinterpret_cast<__half2*>(&uD01.y)); a2 += w01 * t.x; a3 += w01 * t.y;
            t = __half22float2(*reinterpret_cast<__half2*>(&uD10.x)); a0 += w10 * t.x; a1 += w10 * t.y;
            t = __half22float2(*reinterpret_cast<__half2*>(&uD10.y)); a2 += w10 * t.x; a3 += w10 * t.y;
            t = __half22float2(*reinterpret_cast<__half2*>(&uD11.x)); a0 += w11 * t.x; a1 += w11 * t.y;
            t = __half22float2(*reinterpret_cast<__half2*>(&uD11.y)); a2 += w11 * t.x; a3 += w11 * t.y;
        }

        // skewed: idx = c*49 + c/4 + bin -> lane stride 197 (5 mod 32), conflict-free
        int base = clane * NBIN + (clane >> 2) + bin;
        sout[base]            = a0;
        sout[base + NBIN]     = a1;
        sout[base + 2 * NBIN] = a2;
        sout[base + 3 * NBIN] = a3;
    }
    __syncthreads();

    // coalesced writeout: this block owns out[n, half*128 : half*128+128, :, :]
    float* o = out + (size_t)n * (C_ * NBIN) + (size_t)half * CHALF * NBIN;
    #pragma unroll 7
    for (int i = tid; i < CHALF * NBIN; i += 256) {
        int c = i / NBIN;
        o[i] = sout[i + (c >> 2)];
    }
}

extern "C" void kernel_launch(void* const* d_in, const int* in_sizes, int n_in,
                              void* d_out, int out_size)
{
    const float* feat = (const float*)d_in[0];
    const float* rois = (const float*)d_in[1];
    float* out = (float*)d_out;

    dim3 tgrid((W_ + 31) / 32, B_ * H_, C_ / 64);
    dim3 tblock(32, 8);
    transpose_kernel<<<tgrid, tblock>>>(feat);

    int n_rois = in_sizes[1] / 5;
    dim3 ggrid(n_rois, 2);
    roi_gather_kernel<<<ggrid, 256>>>(rois, out);
}

// round 6
// speedup vs baseline: 1.7465x; 1.0710x over previous
#include <cuda_runtime.h>
#include <cuda_fp16.h>

// RoIAlign via NHWC fp16 relayout + table-driven HFMA2 gather.
// feat: (B=2, C=256, H=200, W=336) fp32 NCHW
// rois: (N=1000, 5) [bidx, x1, y1, x2, y2] fp32
// out:  (N, 256, 7, 7) fp32

#define B_    2
#define C_    256
#define H_    200
#define W_    336
#define OUTH  7
#define OUTW  7
#define NBIN  49
#define HWC   (H_ * W_ * C_)
#define CHALF 128

// NHWC fp16 scratch: [B][H][W][C]
__device__ __half g_feat16[(size_t)B_ * HWC];

// ---------------------------------------------------------------------------
// Kernel 1: NCHW fp32 -> NHWC fp16. Block: 64 channels x 32 x-positions.
// ---------------------------------------------------------------------------
__global__ __launch_bounds__(256) void transpose_kernel(const float* __restrict__ feat)
{
    __shared__ float tile[64][33];   // [c][x]

    int xt = blockIdx.x * 32;
    int by = blockIdx.y;             // b*H + y
    int b  = by / H_;
    int y  = by % H_;
    int c0 = blockIdx.z * 64;
    int tx = threadIdx.x;
    int ty = threadIdx.y;

    const float* src = feat + ((size_t)(b * C_ + c0) * H_ + y) * W_;
    int  xg  = xt + tx;
    bool xin = xg < W_;

    #pragma unroll
    for (int k = 0; k < 8; k++) {
        int c = ty + k * 8;
        tile[c][tx] = xin ? __ldg(src + (size_t)c * (H_ * W_) + xg) : 0.0f;
    }
    __syncthreads();

    __half* dst = g_feat16 + ((size_t)(b * H_ + y) * W_) * C_ + c0;
    #pragma unroll
    for (int k = 0; k < 4; k++) {
        int xl = ty + k * 8;
        int x  = xt + xl;
        if (x < W_) {
            __half2 v = __floats2half2_rn(tile[2 * tx][xl], tile[2 * tx + 1][xl]);
            *(__half2*)(dst + (size_t)x * C_ + 2 * tx) = v;
        }
    }
}

// ---------------------------------------------------------------------------
// Kernel 2: gather. grid (N, 2): roi x channel-half. 256 threads = 8 warps.
// One bin per warp per iteration (bins warp, warp+8, ...). Lane covers 4
// channels (uint2 = 8B fp16) -> each corner is one contiguous 256B warp
// request. Per-bin tables of 16 combined corner offsets + packed half2
// weights are precomputed in smem; inner loop is pure LDS/LDG/HFMA2.
// ---------------------------------------------------------------------------
__global__ __launch_bounds__(256, 5) void roi_gather_kernel(
    const float* __restrict__ rois,
    float* __restrict__ out)
{
    __shared__ float sout[CHALF * NBIN + 32];  // skewed: idx = c*49 + c/4 + bin
    __shared__ int   s_ylo[14], s_yhi[14], s_xlo[14], s_xhi[14];
    __shared__ float s_wy0[14], s_wy1[14], s_wx0[14], s_wx1[14];
    __shared__ int   s_off[NBIN * 16];   // combined corner offsets (in halves)
    __shared__ unsigned s_w[NBIN * 16];  // packed (w,w) half2 weights

    int n    = blockIdx.x;
    int half = blockIdx.y;
    int tid  = threadIdx.x;
    int warp = tid >> 5;
    int lane = tid & 31;

    const float* r = rois + n * 5;
    int   b  = (int)__ldg(r + 0);
    float sx = __ldg(r + 1) * 0.25f - 0.5f;
    float sy = __ldg(r + 2) * 0.25f - 0.5f;
    float ex = __ldg(r + 3) * 0.25f - 0.5f;
    float ey = __ldg(r + 4) * 0.25f - 0.5f;
    float bw = (ex - sx) / (float)OUTW;
    float bh = (ey - sy) / (float)OUTH;

    // --- stage 1: 14 y samples, 14 x samples ---
    if (tid < 14) {
        int s  = tid;
        int ph = s >> 1, iy = s & 1;
        float y = sy + ((float)ph + (0.25f + 0.5f * iy)) * bh;
        bool valid = (y > -1.0f) && (y < (float)H_);
        float y0 = fmaxf(y, 0.0f);
        int ylo = (int)floorf(y0);
        int yhi; float ly;
        if (ylo >= H_ - 1) { ylo = H_ - 1; yhi = H_ - 1; ly = 0.0f; }
        else               { yhi = ylo + 1; ly = y0 - (float)ylo; }
        s_ylo[s] = ylo * (W_ * C_);
        s_yhi[s] = yhi * (W_ * C_);
        s_wy0[s] = valid ? (1.0f - ly) * 0.25f : 0.0f;
        s_wy1[s] = valid ? ly * 0.25f : 0.0f;
    } else if (tid >= 64 && tid < 78) {
        int s  = tid - 64;
        int pw = s >> 1, ix = s & 1;
        float x = sx + ((float)pw + (0.25f + 0.5f * ix)) * bw;
        bool valid = (x > -1.0f) && (x < (float)W_);
        float x0 = fmaxf(x, 0.0f);
        int xlo = (int)floorf(x0);
        int xhi; float lx;
        if (xlo >= W_ - 1) { xlo = W_ - 1; xhi = W_ - 1; lx = 0.0f; }
        else               { xhi = xlo + 1; lx = x0 - (float)xlo; }
        s_xlo[s] = xlo * C_;
        s_xhi[s] = xhi * C_;
        s_wx0[s] = valid ? (1.0f - lx) : 0.0f;
        s_wx1[s] = valid ? lx : 0.0f;
    }
    __syncthreads();

    // --- stage 2: fused per-bin corner tables (49 bins x 16 entries) ---
    for (int e = tid; e < NBIN * 16; e += 256) {
        int bin = e >> 4;
        int j   = e & 15;
        int ph  = bin / OUTW;
        int pw  = bin - ph * OUTW;
        int iy = (j >> 3) & 1, ix = (j >> 2) & 1;
        int cy = (j >> 1) & 1, cx = j & 1;
        int syi = ph * 2 + iy;
        int sxi = pw * 2 + ix;
        int   yoff = cy ? s_yhi[syi] : s_ylo[syi];
        int   xoff = cx ? s_xhi[sxi] : s_xlo[sxi];
        float wy   = cy ? s_wy1[syi] : s_wy0[syi];
        float wx   = cx ? s_wx1[sxi] : s_wx0[sxi];
        __half2 h2 = __float2half2_rn(wy * wx);
        s_off[e] = yoff + xoff;
        s_w[e]   = *reinterpret_cast<unsigned*>(&h2);
    }
    __syncthreads();

    // lane -> 4 channels within this half
    int clane = lane * 4;
    const __half* fbase = g_feat16 + (size_t)b * HWC + half * CHALF + clane;

    for (int bin = warp; bin < NBIN; bin += 8) {
        const int*      off = s_off + (bin << 4);
        const unsigned* wp  = s_w   + (bin << 4);

        // 16 independent 8B loads, one batch
        uint2 u[16];
        #pragma unroll
        for (int j = 0; j < 16; j++)
            u[j] = *(const uint2*)(fbase + off[j]);

        float a0 = 0.f, a1 = 0.f, a2 = 0.f, a3 = 0.f;

        #pragma unroll
        for (int s = 0; s < 4; s++) {
            __half2 hl = __floats2half2_rn(0.f, 0.f);
            __half2 hh = hl;
            #pragma unroll
            for (int c = 0; c < 4; c++) {
                int j = s * 4 + c;
                unsigned wraw = wp[j];
                __half2 w = *reinterpret_cast<__half2*>(&wraw);
                hl = __hfma2(w, *reinterpret_cast<__half2*>(&u[j].x), hl);
                hh = __hfma2(w, *reinterpret_cast<__half2*>(&u[j].y), hh);
            }
            float2 fl = __half22float2(hl);
            float2 fh = __half22float2(hh);
            a0 += fl.x; a1 += fl.y; a2 += fh.x; a3 += fh.y;
        }

        // skewed: idx = c*49 + c/4 + bin -> lane stride 197 (5 mod 32), conflict-free
        int base = clane * NBIN + (clane >> 2) + bin;
        sout[base]            = a0;
        sout[base + NBIN]     = a1;
        sout[base + 2 * NBIN] = a2;
        sout[base + 3 * NBIN] = a3;
    }
    __syncthreads();

    // coalesced writeout: this block owns out[n, half*128 : half*128+128, :, :]
    float* o = out + (size_t)n * (C_ * NBIN) + (size_t)half * CHALF * NBIN;
    #pragma unroll 7
    for (int i = tid; i < CHALF * NBIN; i += 256) {
        int c = i / NBIN;
        o[i] = sout[i + (c >> 2)];
    }
}

extern "C" void kernel_launch(void* const* d_in, const int* in_sizes, int n_in,
                              void* d_out, int out_size)
{
    const float* feat = (const float*)d_in[0];
    const float* rois = (const float*)d_in[1];
    float* out = (float*)d_out;

    dim3 tgrid((W_ + 31) / 32, B_ * H_, C_ / 64);
    dim3 tblock(32, 8);
    transpose_kernel<<<tgrid, tblock>>>(feat);

    int n_rois = in_sizes[1] / 5;
    dim3 ggrid(n_rois, 2);
    roi_gather_kernel<<<ggrid, 256>>>(rois, out);
}